// round 2
// baseline (speedup 1.0000x reference)
#include <cuda_runtime.h>
#include <cstdint>

// RVQ: x[B,S,768] f32, codebook[3,16,256] f32, alpha scalar.
// Per token, per head: argmax over 16 codes of (x·k - 0.5*||k||^2),
// out = alpha*x + (1-alpha)*k[best], code = b0 + 16*b1 + 256*b2.

#define NH   3
#define NC   16
#define DHD  256
#define DFULL 768
#define NF4  64            // float4 per code row (256 floats)
#define TPW  3             // tokens per warp (register blocking)
#define NWARPS 4
#define TPB  (TPW * NWARPS) // tokens per tile (12)
#define FULLMASK 0xffffffffu

__device__ __forceinline__ int swz(int j) { return j ^ (j >> 3); }

__global__ void __launch_bounds__(128, 4) rvq_kernel(
    const float* __restrict__ x,
    const float* __restrict__ cb,
    const float* __restrict__ alphap,
    float* __restrict__ out,
    float* __restrict__ code_out,
    int tokens, int write_code, int ntiles)
{
    // Codebook in shared, XOR-swizzled within each 64-float4 row for
    // conflict-free LDS.128 when lane L reads float4s {2L, 2L+1}.
    __shared__ float4 scb[NH * NC * NF4];   // 49152 bytes exactly

    const int tid = threadIdx.x;
    {
        const float4* cbg = (const float4*)cb;
        #pragma unroll
        for (int g = tid; g < NH * NC * NF4; g += 128) {
            int r = g >> 6, j = g & 63;
            scb[(r << 6) + swz(j)] = cbg[g];
        }
    }
    __syncthreads();

    const int lane = tid & 31;
    const int warp = tid >> 5;
    const int cm   = (lane >> 1) & 15;   // code this lane owns after reduce

    // Per-lane half-norms of its mapped code, per head.
    // Rotate start index by cm to avoid 16-way bank serialization.
    float hn[NH];
    #pragma unroll
    for (int h = 0; h < NH; h++) {
        const float4* row = &scb[(h * NC + cm) << 6];
        float s = 0.f;
        #pragma unroll
        for (int j = 0; j < NF4; j++) {
            int jj = (j + cm) & 63;
            float4 k = row[swz(jj)];
            s = fmaf(k.x, k.x, s);
            s = fmaf(k.y, k.y, s);
            s = fmaf(k.z, k.z, s);
            s = fmaf(k.w, k.w, s);
        }
        hn[h] = 0.5f * s;
    }

    const float alpha = *alphap;
    const float beta  = 1.0f - alpha;

    for (int tile = blockIdx.x; tile < ntiles; tile += gridDim.x) {
        const long long t0 = (long long)tile * TPB + warp * TPW;
        int pack[TPW];
        #pragma unroll
        for (int t = 0; t < TPW; t++) pack[t] = 0;

        #pragma unroll
        for (int h = 0; h < NH; h++) {
            // Load x chunks for TPW tokens: lane holds 8 dims of head h.
            float4 xa[TPW], xb[TPW];
            #pragma unroll
            for (int t = 0; t < TPW; t++) {
                if (t0 + t < tokens) {
                    const float4* xp =
                        (const float4*)(x + (size_t)(t0 + t) * DFULL + h * DHD)
                        + (lane << 1);
                    xa[t] = xp[0];
                    xb[t] = xp[1];
                } else {
                    xa[t] = make_float4(0.f, 0.f, 0.f, 0.f);
                    xb[t] = xa[t];
                }
            }

            // Partial dots: acc[t][c] = sum over this lane's 8 dims.
            float acc[TPW][NC];
            #pragma unroll
            for (int t = 0; t < TPW; t++)
                #pragma unroll
                for (int c = 0; c < NC; c++) acc[t][c] = 0.f;

            #pragma unroll
            for (int c = 0; c < NC; c++) {
                const float4* row = &scb[(h * NC + c) << 6];
                float4 ka = row[swz(2 * lane)];
                float4 kb = row[swz(2 * lane + 1)];
                #pragma unroll
                for (int t = 0; t < TPW; t++) {
                    float a = acc[t][c];
                    a = fmaf(xa[t].x, ka.x, a);
                    a = fmaf(xa[t].y, ka.y, a);
                    a = fmaf(xa[t].z, ka.z, a);
                    a = fmaf(xa[t].w, ka.w, a);
                    a = fmaf(xb[t].x, kb.x, a);
                    a = fmaf(xb[t].y, kb.y, a);
                    a = fmaf(xb[t].z, kb.z, a);
                    a = fmaf(xb[t].w, kb.w, a);
                    acc[t][c] = a;
                }
            }

            // Per token: multi-value split-exchange reduction (16 shfl),
            // then 5-stage argmax butterfly (10 shfl).
            #pragma unroll
            for (int t = 0; t < TPW; t++) {
                float w8[8];
                {
                    const bool up = (lane & 16) != 0;
                    #pragma unroll
                    for (int j = 0; j < 8; j++) {
                        float send = up ? acc[t][j]     : acc[t][j + 8];
                        float keep = up ? acc[t][j + 8] : acc[t][j];
                        w8[j] = keep + __shfl_xor_sync(FULLMASK, send, 16);
                    }
                }
                float w4[4];
                {
                    const bool up = (lane & 8) != 0;
                    #pragma unroll
                    for (int j = 0; j < 4; j++) {
                        float send = up ? w8[j]     : w8[j + 4];
                        float keep = up ? w8[j + 4] : w8[j];
                        w4[j] = keep + __shfl_xor_sync(FULLMASK, send, 8);
                    }
                }
                float w2[2];
                {
                    const bool up = (lane & 4) != 0;
                    #pragma unroll
                    for (int j = 0; j < 2; j++) {
                        float send = up ? w4[j]     : w4[j + 2];
                        float keep = up ? w4[j + 2] : w4[j];
                        w2[j] = keep + __shfl_xor_sync(FULLMASK, send, 4);
                    }
                }
                float w1;
                {
                    const bool up = (lane & 2) != 0;
                    float send = up ? w2[0] : w2[1];
                    float keep = up ? w2[1] : w2[0];
                    w1 = keep + __shfl_xor_sync(FULLMASK, send, 2);
                }
                w1 += __shfl_xor_sync(FULLMASK, w1, 1);

                float sc = w1 - hn[h];  // lane holds score of code cm
                int   bi = cm;
                #pragma unroll
                for (int m = 1; m < 32; m <<= 1) {
                    float so = __shfl_xor_sync(FULLMASK, sc, m);
                    int   io = __shfl_xor_sync(FULLMASK, bi, m);
                    if (so > sc || (so == sc && io < bi)) { sc = so; bi = io; }
                }
                pack[t] += bi << (4 * h);

                if (t0 + t < tokens) {
                    const float4* row = &scb[(h * NC + bi) << 6];
                    float4 ka = row[swz(2 * lane)];
                    float4 kb = row[swz(2 * lane + 1)];
                    float4 oa, ob;
                    oa.x = fmaf(alpha, xa[t].x, beta * ka.x);
                    oa.y = fmaf(alpha, xa[t].y, beta * ka.y);
                    oa.z = fmaf(alpha, xa[t].z, beta * ka.z);
                    oa.w = fmaf(alpha, xa[t].w, beta * ka.w);
                    ob.x = fmaf(alpha, xb[t].x, beta * kb.x);
                    ob.y = fmaf(alpha, xb[t].y, beta * kb.y);
                    ob.z = fmaf(alpha, xb[t].z, beta * kb.z);
                    ob.w = fmaf(alpha, xb[t].w, beta * kb.w);
                    float4* op =
                        (float4*)(out + (size_t)(t0 + t) * DFULL + h * DHD)
                        + (lane << 1);
                    op[0] = oa;
                    op[1] = ob;
                }
            }
        }

        if (write_code && lane == 0) {
            #pragma unroll
            for (int t = 0; t < TPW; t++)
                if (t0 + t < tokens)
                    code_out[t0 + t] = (float)pack[t];
        }
    }
}

extern "C" void kernel_launch(void* const* d_in, const int* in_sizes, int n_in,
                              void* d_out, int out_size)
{
    const float* x      = (const float*)d_in[0];
    const float* kernel = (const float*)d_in[1];
    const float* alpha  = (const float*)d_in[2];
    float* out = (float*)d_out;

    const int tokens = in_sizes[0] / DFULL;        // B*S
    const int ntiles = (tokens + TPB - 1) / TPB;

    // Output buffer: [tokens*768] blend, then [tokens] packed code (as f32).
    const long long out_elems = (long long)tokens * DFULL;
    int write_code = (out_size >= out_elems + tokens) ? 1 : 0;
    float* code_out = out + out_elems;

    int grid = ntiles < 608 ? ntiles : 608;   // ~4 blocks/SM, persistent tiles
    rvq_kernel<<<grid, 128>>>(x, kernel, alpha, out, code_out,
                              tokens, write_code, ntiles);
}